// round 9
// baseline (speedup 1.0000x reference)
#include <cuda_runtime.h>
#include <cuda_bf16.h>

#define IMG_H 512
#define IMG_W 512
#define TW 64
#define TH 32
#define NT 256

#define SP 76   // sS: 40 rows (72 valid cols, halo 4)
#define BP 76   // sB: 38 rows (70 valid cols, halo 3)   [border path]
#define GP 76   // sG: 36 rows (68 valid cols, halo 2)
#define TP 72   // sT: 34 rows (66 valid cols, halo 1)   [border path]

#define HW (IMG_H * IMG_W)

// wbuf layout:
// [0:9) gauss  [9:18) sobel_x  [18:27) sobel_y  [27:36) D=sum_k dir_k  [36:45) nms P
// [45:70) W5X=conv2f(G,Sx)  [70:95) W5Y=conv2f(G,Sy)  [95:120) W5T=conv2f(D,P)

__global__ __launch_bounds__(NT, 4) void canny_fused(
    const float* __restrict__ img,
    const float* __restrict__ gw,
    const float* __restrict__ sxw,
    const float* __restrict__ syw,
    const float* __restrict__ dw,
    const float* __restrict__ nw,
    float* __restrict__ out,
    int C, float invC)
{
    __shared__ float buf1[40 * SP];
    __shared__ float buf2[38 * BP];
    __shared__ float wbuf[120];

    float* const sS = buf1;

    const int tid = threadIdx.x;
    const int b  = blockIdx.z;
    const int x0 = blockIdx.x * TW;
    const int y0 = blockIdx.y * TH;
    const bool interior = (x0 > 0) && (x0 + TW < IMG_W) && (y0 > 0) && (y0 + TH < IMG_H);

    // ---- base weights (from global) ----
    if (tid < 45) {
        float v;
        if (tid < 9)       v = gw[tid];
        else if (tid < 18) v = sxw[tid - 9];
        else if (tid < 27) v = syw[tid - 18];
        else if (tid < 36) {
            int j = tid - 27;
            v = 0.f;
            #pragma unroll
            for (int k = 0; k < 8; k++) v += dw[k * 9 + j];
        } else             v = nw[tid - 36];
        wbuf[tid] = v;
    } else if (tid < 120) {
        // ---- 5x5 composites, computed straight from global (no barrier needed) ----
        int t = tid - 45;
        int which = t / 25, idx = t - which * 25;
        int a = idx / 5, bb = idx - a * 5;
        float s = 0.f;
        #pragma unroll
        for (int i = 0; i < 3; i++)
            #pragma unroll
            for (int j = 0; j < 3; j++) {
                int u = a - i, v = bb - j;
                if (u >= 0 && u < 3 && v >= 0 && v < 3) {
                    float k1, k2;
                    if (which == 0)      { k1 = gw[i * 3 + j];  k2 = sxw[u * 3 + v]; }
                    else if (which == 1) { k1 = gw[i * 3 + j];  k2 = syw[u * 3 + v]; }
                    else {
                        float d = 0.f;
                        #pragma unroll
                        for (int k = 0; k < 8; k++) d += dw[k * 9 + i * 3 + j];
                        k1 = d; k2 = nw[u * 3 + v];
                    }
                    s += k1 * k2;
                }
            }
        wbuf[45 + t] = s;
    }

    // ---- load s = channel sum, halo 4, float4 granularity ----
    {
        const float* ib = img + (size_t)b * C * HW;
        if (interior) {
            for (int it = tid; it < 40 * 19; it += NT) {
                int p = it / 19, q = it - p * 19;
                const float* pp = ib + (size_t)(y0 + p - 4) * IMG_W + (x0 + q * 4 - 4);
                float v0 = 0.f, v1 = 0.f, v2 = 0.f, v3 = 0.f;
                for (int ch = 0; ch < C; ch++) {
                    float4 t = *(const float4*)(pp + (size_t)ch * HW);
                    v0 += t.x; v1 += t.y; v2 += t.z; v3 += t.w;
                }
                *(float4*)&sS[p * SP + q * 4] = make_float4(v0, v1, v2, v3);
            }
        } else {
            for (int it = tid; it < 40 * 19; it += NT) {
                int p = it / 19, q = it - p * 19;
                int py = y0 + p - 4;
                int px = x0 + q * 4 - 4;
                float v[4] = {0.f, 0.f, 0.f, 0.f};
                if ((unsigned)py < (unsigned)IMG_H) {
                    if (px >= 0 && px + 3 < IMG_W) {
                        const float* pp = ib + (size_t)py * IMG_W + px;
                        for (int ch = 0; ch < C; ch++) {
                            float4 t = *(const float4*)(pp + (size_t)ch * HW);
                            v[0] += t.x; v[1] += t.y; v[2] += t.z; v[3] += t.w;
                        }
                    } else {
                        #pragma unroll
                        for (int j = 0; j < 4; j++) {
                            int xx = px + j;
                            if ((unsigned)xx < (unsigned)IMG_W) {
                                float s = 0.f;
                                for (int ch = 0; ch < C; ch++)
                                    s += ib[(size_t)ch * HW + (size_t)py * IMG_W + xx];
                                v[j] = s;
                            }
                        }
                    }
                }
                *(float4*)&sS[p * SP + q * 4] = make_float4(v[0], v[1], v[2], v[3]);
            }
        }
    }
    __syncthreads();

    if (interior) {
        float* const sG = buf2;   // buf2 free on interior path

        // ---- stage A: dual 5x5 composite (gx,gy) + magnitude -> sG, 4w x 2h ----
        for (int it = tid; it < 18 * 17; it += NT) {
            int rp = it / 17, g = it - rp * 17;
            int r = rp * 2, c = g * 4;
            float xa0[4] = {0,0,0,0}, ya0[4] = {0,0,0,0};
            float xa1[4] = {0,0,0,0}, ya1[4] = {0,0,0,0};
            #pragma unroll
            for (int i = 0; i < 6; i++) {
                float t[8];
                *(float4*)&t[0] = *(const float4*)&sS[(r + i) * SP + c];
                *(float4*)&t[4] = *(const float4*)&sS[(r + i) * SP + c + 4];
                if (i < 5) {
                    #pragma unroll
                    for (int v = 0; v < 5; v++) {
                        float wx = wbuf[45 + i * 5 + v];
                        float wy = wbuf[70 + i * 5 + v];
                        #pragma unroll
                        for (int j = 0; j < 4; j++) {
                            xa0[j] += wx * t[j + v];
                            ya0[j] += wy * t[j + v];
                        }
                    }
                }
                if (i > 0) {
                    #pragma unroll
                    for (int v = 0; v < 5; v++) {
                        float wx = wbuf[45 + (i - 1) * 5 + v];
                        float wy = wbuf[70 + (i - 1) * 5 + v];
                        #pragma unroll
                        for (int j = 0; j < 4; j++) {
                            xa1[j] += wx * t[j + v];
                            ya1[j] += wy * t[j + v];
                        }
                    }
                }
            }
            float v0[4], v1[4];
            #pragma unroll
            for (int j = 0; j < 4; j++) {
                v0[j] = sqrtf(xa0[j]*xa0[j] + ya0[j]*ya0[j]) * invC;
                v1[j] = sqrtf(xa1[j]*xa1[j] + ya1[j]*ya1[j]) * invC;
            }
            *(float4*)&sG[r * GP + c]       = make_float4(v0[0], v0[1], v0[2], v0[3]);
            *(float4*)&sG[(r + 1) * GP + c] = make_float4(v1[0], v1[1], v1[2], v1[3]);
        }
        __syncthreads();

        // ---- stage C: 5x5 composite W5T = D*P -> out, 8w x 2h ----
        if (tid < 16 * 8) {
            int rp = tid >> 3, g = tid & 7;
            int r = rp * 2, c = g * 8;
            float o0[8] = {0,0,0,0,0,0,0,0}, o1[8] = {0,0,0,0,0,0,0,0};
            float wp[5];
            #pragma unroll
            for (int i = 0; i < 6; i++) {
                float t[12];
                *(float4*)&t[0] = *(const float4*)&sG[(r + i) * GP + c];
                *(float4*)&t[4] = *(const float4*)&sG[(r + i) * GP + c + 4];
                *(float4*)&t[8] = *(const float4*)&sG[(r + i) * GP + c + 8];
                if (i > 0) {
                    #pragma unroll
                    for (int j = 0; j < 8; j++)
                        o1[j] += wp[0]*t[j] + wp[1]*t[j+1] + wp[2]*t[j+2]
                               + wp[3]*t[j+3] + wp[4]*t[j+4];
                }
                if (i < 5) {
                    float wc[5];
                    #pragma unroll
                    for (int v = 0; v < 5; v++) wc[v] = wbuf[95 + i * 5 + v];
                    #pragma unroll
                    for (int j = 0; j < 8; j++)
                        o0[j] += wc[0]*t[j] + wc[1]*t[j+1] + wc[2]*t[j+2]
                               + wc[3]*t[j+3] + wc[4]*t[j+4];
                    #pragma unroll
                    for (int v = 0; v < 5; v++) wp[v] = wc[v];
                }
            }
            float* ob = out + (size_t)b * HW + (size_t)(y0 + r) * IMG_W + x0 + c;
            *(float4*)ob               = make_float4(o0[0], o0[1], o0[2], o0[3]);
            *(float4*)(ob + 4)         = make_float4(o0[4], o0[5], o0[6], o0[7]);
            *(float4*)(ob + IMG_W)     = make_float4(o1[0], o1[1], o1[2], o1[3]);
            *(float4*)(ob + IMG_W + 4) = make_float4(o1[4], o1[5], o1[6], o1[7]);
        }
    } else {
        // ================= border path: exact staged pipeline =================
        float* const sB = buf2;
        float* const sG = buf1;
        float* const sT = buf2;

        // ---- stage 1: gaussian blur -> sB (halo 3), 8w x 2h ----
        if (tid < 19 * 9) {
            float w[9];
            #pragma unroll
            for (int i = 0; i < 9; i++) w[i] = wbuf[i];
            int rp = tid / 9, g = tid - rp * 9;
            int r = rp * 2, c = g * 8;
            float v0[8] = {0,0,0,0,0,0,0,0}, v1[8] = {0,0,0,0,0,0,0,0};
            #pragma unroll
            for (int i = 0; i < 4; i++) {
                float t[12];
                *(float4*)&t[0] = *(const float4*)&sS[(r + i) * SP + c];
                *(float4*)&t[4] = *(const float4*)&sS[(r + i) * SP + c + 4];
                *(float4*)&t[8] = *(const float4*)&sS[(r + i) * SP + c + 8];
                if (i < 3) {
                    #pragma unroll
                    for (int j = 0; j < 8; j++)
                        v0[j] += w[i*3]*t[j] + w[i*3+1]*t[j+1] + w[i*3+2]*t[j+2];
                }
                if (i > 0) {
                    #pragma unroll
                    for (int j = 0; j < 8; j++)
                        v1[j] += w[(i-1)*3]*t[j] + w[(i-1)*3+1]*t[j+1] + w[(i-1)*3+2]*t[j+2];
                }
            }
            int py = y0 + r - 3, px = x0 + c - 3;
            bool iny0 = (unsigned)py       < (unsigned)IMG_H;
            bool iny1 = (unsigned)(py + 1) < (unsigned)IMG_H;
            #pragma unroll
            for (int j = 0; j < 8; j++) {
                bool inx = (unsigned)(px + j) < (unsigned)IMG_W;
                v0[j] = (iny0 && inx) ? v0[j] : 0.f;
                v1[j] = (iny1 && inx) ? v1[j] : 0.f;
            }
            *(float4*)&sB[r * BP + c]           = make_float4(v0[0], v0[1], v0[2], v0[3]);
            *(float4*)&sB[r * BP + c + 4]       = make_float4(v0[4], v0[5], v0[6], v0[7]);
            *(float4*)&sB[(r + 1) * BP + c]     = make_float4(v1[0], v1[1], v1[2], v1[3]);
            *(float4*)&sB[(r + 1) * BP + c + 4] = make_float4(v1[4], v1[5], v1[6], v1[7]);
        }
        __syncthreads();

        // ---- stage 2: sobel + magnitude -> sG (halo 2), 4w x 2h ----
        {
            float wx[9], wy[9];
            #pragma unroll
            for (int i = 0; i < 9; i++) { wx[i] = wbuf[9 + i]; wy[i] = wbuf[18 + i]; }
            for (int it = tid; it < 18 * 17; it += NT) {
                int rp = it / 17, g = it - rp * 17;
                int r = rp * 2, c = g * 4;
                float gx0[4] = {0,0,0,0}, gy0[4] = {0,0,0,0};
                float gx1[4] = {0,0,0,0}, gy1[4] = {0,0,0,0};
                #pragma unroll
                for (int i = 0; i < 4; i++) {
                    float t[8];
                    *(float4*)&t[0] = *(const float4*)&sB[(r + i) * BP + c];
                    *(float4*)&t[4] = *(const float4*)&sB[(r + i) * BP + c + 4];
                    if (i < 3) {
                        #pragma unroll
                        for (int j = 0; j < 4; j++) {
                            gx0[j] += wx[i*3]*t[j] + wx[i*3+1]*t[j+1] + wx[i*3+2]*t[j+2];
                            gy0[j] += wy[i*3]*t[j] + wy[i*3+1]*t[j+1] + wy[i*3+2]*t[j+2];
                        }
                    }
                    if (i > 0) {
                        #pragma unroll
                        for (int j = 0; j < 4; j++) {
                            gx1[j] += wx[(i-1)*3]*t[j] + wx[(i-1)*3+1]*t[j+1] + wx[(i-1)*3+2]*t[j+2];
                            gy1[j] += wy[(i-1)*3]*t[j] + wy[(i-1)*3+1]*t[j+1] + wy[(i-1)*3+2]*t[j+2];
                        }
                    }
                }
                int py = y0 + r - 2, px = x0 + c - 2;
                bool iny0 = (unsigned)py       < (unsigned)IMG_H;
                bool iny1 = (unsigned)(py + 1) < (unsigned)IMG_H;
                float v0[4], v1[4];
                #pragma unroll
                for (int j = 0; j < 4; j++) {
                    bool inx = (unsigned)(px + j) < (unsigned)IMG_W;
                    float m0 = sqrtf(gx0[j]*gx0[j] + gy0[j]*gy0[j]) * invC;
                    float m1 = sqrtf(gx1[j]*gx1[j] + gy1[j]*gy1[j]) * invC;
                    v0[j] = (iny0 && inx) ? m0 : 0.f;
                    v1[j] = (iny1 && inx) ? m1 : 0.f;
                }
                *(float4*)&sG[r * GP + c]       = make_float4(v0[0], v0[1], v0[2], v0[3]);
                *(float4*)&sG[(r + 1) * GP + c] = make_float4(v1[0], v1[1], v1[2], v1[3]);
            }
        }
        __syncthreads();

        // ---- stage 3: D conv -> sT (halo 1), 8w x 2h ----
        if (tid < 17 * 9) {
            float w[9];
            #pragma unroll
            for (int i = 0; i < 9; i++) w[i] = wbuf[27 + i];
            int rp = tid / 9, g = tid - rp * 9;
            int r = rp * 2, c = g * 8;
            float v0[8] = {0,0,0,0,0,0,0,0}, v1[8] = {0,0,0,0,0,0,0,0};
            #pragma unroll
            for (int i = 0; i < 4; i++) {
                float t[12];
                *(float4*)&t[0] = *(const float4*)&sG[(r + i) * GP + c];
                *(float4*)&t[4] = *(const float4*)&sG[(r + i) * GP + c + 4];
                *(float4*)&t[8] = *(const float4*)&sG[(r + i) * GP + c + 8];
                if (i < 3) {
                    #pragma unroll
                    for (int j = 0; j < 8; j++)
                        v0[j] += w[i*3]*t[j] + w[i*3+1]*t[j+1] + w[i*3+2]*t[j+2];
                }
                if (i > 0) {
                    #pragma unroll
                    for (int j = 0; j < 8; j++)
                        v1[j] += w[(i-1)*3]*t[j] + w[(i-1)*3+1]*t[j+1] + w[(i-1)*3+2]*t[j+2];
                }
            }
            int py = y0 + r - 1, px = x0 + c - 1;
            bool iny0 = (unsigned)py       < (unsigned)IMG_H;
            bool iny1 = (unsigned)(py + 1) < (unsigned)IMG_H;
            #pragma unroll
            for (int j = 0; j < 8; j++) {
                bool inx = (unsigned)(px + j) < (unsigned)IMG_W;
                v0[j] = (iny0 && inx) ? v0[j] : 0.f;
                v1[j] = (iny1 && inx) ? v1[j] : 0.f;
            }
            *(float4*)&sT[r * TP + c]           = make_float4(v0[0], v0[1], v0[2], v0[3]);
            *(float4*)&sT[r * TP + c + 4]       = make_float4(v0[4], v0[5], v0[6], v0[7]);
            *(float4*)&sT[(r + 1) * TP + c]     = make_float4(v1[0], v1[1], v1[2], v1[3]);
            *(float4*)&sT[(r + 1) * TP + c + 4] = make_float4(v1[4], v1[5], v1[6], v1[7]);
        }
        __syncthreads();

        // ---- stage 4: nms pattern conv -> out, 8w x 2h ----
        if (tid < 16 * 8) {
            float w[9];
            #pragma unroll
            for (int i = 0; i < 9; i++) w[i] = wbuf[36 + i];
            int rp = tid >> 3, g = tid & 7;
            int r = rp * 2, c = g * 8;
            float v0[8] = {0,0,0,0,0,0,0,0}, v1[8] = {0,0,0,0,0,0,0,0};
            #pragma unroll
            for (int i = 0; i < 4; i++) {
                float t[12];
                *(float4*)&t[0] = *(const float4*)&sT[(r + i) * TP + c];
                *(float4*)&t[4] = *(const float4*)&sT[(r + i) * TP + c + 4];
                *(float4*)&t[8] = *(const float4*)&sT[(r + i) * TP + c + 8];
                if (i < 3) {
                    #pragma unroll
                    for (int j = 0; j < 8; j++)
                        v0[j] += w[i*3]*t[j] + w[i*3+1]*t[j+1] + w[i*3+2]*t[j+2];
                }
                if (i > 0) {
                    #pragma unroll
                    for (int j = 0; j < 8; j++)
                        v1[j] += w[(i-1)*3]*t[j] + w[(i-1)*3+1]*t[j+1] + w[(i-1)*3+2]*t[j+2];
                }
            }
            float* ob = out + (size_t)b * HW + (size_t)(y0 + r) * IMG_W + x0 + c;
            *(float4*)ob                 = make_float4(v0[0], v0[1], v0[2], v0[3]);
            *(float4*)(ob + 4)           = make_float4(v0[4], v0[5], v0[6], v0[7]);
            *(float4*)(ob + IMG_W)       = make_float4(v1[0], v1[1], v1[2], v1[3]);
            *(float4*)(ob + IMG_W + 4)   = make_float4(v1[4], v1[5], v1[6], v1[7]);
        }
    }
}

extern "C" void kernel_launch(void* const* d_in, const int* in_sizes, int n_in,
                              void* d_out, int out_size) {
    const float* img = (const float*)d_in[0];
    const float* gw  = (const float*)d_in[1];
    const float* sxw = (const float*)d_in[2];
    const float* syw = (const float*)d_in[3];
    const float* dw  = (const float*)d_in[4];
    const float* nw  = (const float*)d_in[5];
    float* out = (float*)d_out;

    int C = in_sizes[1] / 9;
    if (C < 1) C = 1;
    int B = in_sizes[0] / (C * HW);
    if (B < 1) B = 1;

    dim3 grid(IMG_W / TW, IMG_H / TH, B);
    canny_fused<<<grid, NT>>>(img, gw, sxw, syw, dw, nw, out, C, 1.0f / (float)C);
}

// round 10
// speedup vs baseline: 1.1750x; 1.1750x over previous
#include <cuda_runtime.h>
#include <cuda_bf16.h>
#include <cuda_fp16.h>

#define IMG_H 512
#define IMG_W 512
#define TW 64
#define TH 32
#define NT 256

#define SP 76   // sS: 40 rows (72 valid cols, halo 4)
#define BP 76   // sB: 38 rows (70 valid cols, halo 3)
#define GP 76   // sG: 36 rows (68 valid cols, halo 2)  (fp32 border / fp16 interior)
#define TP 72   // sT: 34 rows (66 valid cols, halo 1)  [border path]

#define HW (IMG_H * IMG_W)

__global__ __launch_bounds__(NT, 4) void canny_fused(
    const float* __restrict__ img,
    const float* __restrict__ gw,
    const float* __restrict__ sxw,
    const float* __restrict__ syw,
    const float* __restrict__ dw,
    const float* __restrict__ nw,
    float* __restrict__ out,
    int C, float invC)
{
    // buf1: sS, then sG (fp32 border / half interior). buf2: sB, then sT (border).
    __shared__ float buf1[40 * SP];
    __shared__ float buf2[38 * BP];
    __shared__ float wbuf[70];  // [0:9) G [9:18) Sx [18:27) Sy [27:36) D [36:45) P
                                // [45:70) W5T = full_conv2(D, P)

    float* const sS = buf1;
    float* const sB = buf2;

    const int tid = threadIdx.x;
    const int b  = blockIdx.z;
    const int x0 = blockIdx.x * TW;
    const int y0 = blockIdx.y * TH;
    const bool interior = (x0 > 0) && (x0 + TW < IMG_W) && (y0 > 0) && (y0 + TH < IMG_H);

    // ---- weights ----
    if (tid < 45) {
        float v;
        if (tid < 9)       v = gw[tid];
        else if (tid < 18) v = sxw[tid - 9];
        else if (tid < 27) v = syw[tid - 18];
        else if (tid < 36) {
            int j = tid - 27;
            v = 0.f;
            #pragma unroll
            for (int k = 0; k < 8; k++) v += dw[k * 9 + j];
        } else             v = nw[tid - 36];
        wbuf[tid] = v;
    }

    // ---- load s = channel sum, halo 4, float4 granularity ----
    {
        const float* ib = img + (size_t)b * C * HW;
        if (interior) {
            for (int it = tid; it < 40 * 19; it += NT) {
                int p = it / 19, q = it - p * 19;
                const float* pp = ib + (size_t)(y0 + p - 4) * IMG_W + (x0 + q * 4 - 4);
                float v0 = 0.f, v1 = 0.f, v2 = 0.f, v3 = 0.f;
                for (int ch = 0; ch < C; ch++) {
                    float4 t = *(const float4*)(pp + (size_t)ch * HW);
                    v0 += t.x; v1 += t.y; v2 += t.z; v3 += t.w;
                }
                *(float4*)&sS[p * SP + q * 4] = make_float4(v0, v1, v2, v3);
            }
        } else {
            for (int it = tid; it < 40 * 19; it += NT) {
                int p = it / 19, q = it - p * 19;
                int py = y0 + p - 4;
                int px = x0 + q * 4 - 4;
                float v[4] = {0.f, 0.f, 0.f, 0.f};
                if ((unsigned)py < (unsigned)IMG_H) {
                    if (px >= 0 && px + 3 < IMG_W) {
                        const float* pp = ib + (size_t)py * IMG_W + px;
                        for (int ch = 0; ch < C; ch++) {
                            float4 t = *(const float4*)(pp + (size_t)ch * HW);
                            v[0] += t.x; v[1] += t.y; v[2] += t.z; v[3] += t.w;
                        }
                    } else {
                        #pragma unroll
                        for (int j = 0; j < 4; j++) {
                            int xx = px + j;
                            if ((unsigned)xx < (unsigned)IMG_W) {
                                float s = 0.f;
                                for (int ch = 0; ch < C; ch++)
                                    s += ib[(size_t)ch * HW + (size_t)py * IMG_W + xx];
                                v[j] = s;
                            }
                        }
                    }
                }
                *(float4*)&sS[p * SP + q * 4] = make_float4(v[0], v[1], v[2], v[3]);
            }
        }
    }
    __syncthreads();

    // ---- composite W5T = full_conv2(D, P), 25 threads ----
    if (tid < 25) {
        int a = tid / 5, bb = tid - a * 5;
        float s = 0.f;
        #pragma unroll
        for (int i = 0; i < 3; i++)
            #pragma unroll
            for (int j = 0; j < 3; j++) {
                int u = a - i, v = bb - j;
                if (u >= 0 && u < 3 && v >= 0 && v < 3)
                    s += wbuf[27 + i * 3 + j] * wbuf[36 + u * 3 + v];
            }
        wbuf[45 + tid] = s;
    }

    // ---- stage 1: gaussian blur -> sB (halo 3), 8w x 2h ----
    if (tid < 19 * 9) {
        float w[9];
        #pragma unroll
        for (int i = 0; i < 9; i++) w[i] = wbuf[i];
        int rp = tid / 9, g = tid - rp * 9;
        int r = rp * 2, c = g * 8;
        float v0[8] = {0,0,0,0,0,0,0,0}, v1[8] = {0,0,0,0,0,0,0,0};
        #pragma unroll
        for (int i = 0; i < 4; i++) {
            float t[12];
            *(float4*)&t[0] = *(const float4*)&sS[(r + i) * SP + c];
            *(float4*)&t[4] = *(const float4*)&sS[(r + i) * SP + c + 4];
            *(float4*)&t[8] = *(const float4*)&sS[(r + i) * SP + c + 8];
            if (i < 3) {
                #pragma unroll
                for (int j = 0; j < 8; j++)
                    v0[j] += w[i*3]*t[j] + w[i*3+1]*t[j+1] + w[i*3+2]*t[j+2];
            }
            if (i > 0) {
                #pragma unroll
                for (int j = 0; j < 8; j++)
                    v1[j] += w[(i-1)*3]*t[j] + w[(i-1)*3+1]*t[j+1] + w[(i-1)*3+2]*t[j+2];
            }
        }
        int py = y0 + r - 3, px = x0 + c - 3;
        bool iny0 = (unsigned)py       < (unsigned)IMG_H;
        bool iny1 = (unsigned)(py + 1) < (unsigned)IMG_H;
        #pragma unroll
        for (int j = 0; j < 8; j++) {
            bool inx = (unsigned)(px + j) < (unsigned)IMG_W;
            v0[j] = (iny0 && inx) ? v0[j] : 0.f;
            v1[j] = (iny1 && inx) ? v1[j] : 0.f;
        }
        *(float4*)&sB[r * BP + c]           = make_float4(v0[0], v0[1], v0[2], v0[3]);
        *(float4*)&sB[r * BP + c + 4]       = make_float4(v0[4], v0[5], v0[6], v0[7]);
        *(float4*)&sB[(r + 1) * BP + c]     = make_float4(v1[0], v1[1], v1[2], v1[3]);
        *(float4*)&sB[(r + 1) * BP + c + 4] = make_float4(v1[4], v1[5], v1[6], v1[7]);
    }
    __syncthreads();

    // ---- stage 2: sobel + magnitude -> sG (halo 2), 4w x 2h ----
    // Interior blocks store sG as HALF (halves stage-C read bytes); border fp32.
    {
        float wx[9], wy[9];
        #pragma unroll
        for (int i = 0; i < 9; i++) { wx[i] = wbuf[9 + i]; wy[i] = wbuf[18 + i]; }
        float* const sGf = buf1;
        __half* const sGh = (__half*)buf1;
        for (int it = tid; it < 18 * 17; it += NT) {
            int rp = it / 17, g = it - rp * 17;
            int r = rp * 2, c = g * 4;
            float gx0[4] = {0,0,0,0}, gy0[4] = {0,0,0,0};
            float gx1[4] = {0,0,0,0}, gy1[4] = {0,0,0,0};
            #pragma unroll
            for (int i = 0; i < 4; i++) {
                float t[8];
                *(float4*)&t[0] = *(const float4*)&sB[(r + i) * BP + c];
                *(float4*)&t[4] = *(const float4*)&sB[(r + i) * BP + c + 4];
                if (i < 3) {
                    #pragma unroll
                    for (int j = 0; j < 4; j++) {
                        gx0[j] += wx[i*3]*t[j] + wx[i*3+1]*t[j+1] + wx[i*3+2]*t[j+2];
                        gy0[j] += wy[i*3]*t[j] + wy[i*3+1]*t[j+1] + wy[i*3+2]*t[j+2];
                    }
                }
                if (i > 0) {
                    #pragma unroll
                    for (int j = 0; j < 4; j++) {
                        gx1[j] += wx[(i-1)*3]*t[j] + wx[(i-1)*3+1]*t[j+1] + wx[(i-1)*3+2]*t[j+2];
                        gy1[j] += wy[(i-1)*3]*t[j] + wy[(i-1)*3+1]*t[j+1] + wy[(i-1)*3+2]*t[j+2];
                    }
                }
            }
            int py = y0 + r - 2, px = x0 + c - 2;
            bool iny0 = (unsigned)py       < (unsigned)IMG_H;
            bool iny1 = (unsigned)(py + 1) < (unsigned)IMG_H;
            float v0[4], v1[4];
            #pragma unroll
            for (int j = 0; j < 4; j++) {
                bool inx = (unsigned)(px + j) < (unsigned)IMG_W;
                float m0 = sqrtf(gx0[j]*gx0[j] + gy0[j]*gy0[j]) * invC;
                float m1 = sqrtf(gx1[j]*gx1[j] + gy1[j]*gy1[j]) * invC;
                v0[j] = (iny0 && inx) ? m0 : 0.f;
                v1[j] = (iny1 && inx) ? m1 : 0.f;
            }
            if (interior) {
                *(__half2*)&sGh[r * GP + c]           = __floats2half2_rn(v0[0], v0[1]);
                *(__half2*)&sGh[r * GP + c + 2]       = __floats2half2_rn(v0[2], v0[3]);
                *(__half2*)&sGh[(r + 1) * GP + c]     = __floats2half2_rn(v1[0], v1[1]);
                *(__half2*)&sGh[(r + 1) * GP + c + 2] = __floats2half2_rn(v1[2], v1[3]);
            } else {
                *(float4*)&sGf[r * GP + c]       = make_float4(v0[0], v0[1], v0[2], v0[3]);
                *(float4*)&sGf[(r + 1) * GP + c] = make_float4(v1[0], v1[1], v1[2], v1[3]);
            }
        }
    }
    __syncthreads();

    if (interior) {
        // ---- stage C: 5x5 composite W5T = D*P over half sG -> out, 8w x 2h ----
        const __half* sGh = (const __half*)buf1;
        if (tid < 16 * 8) {
            int rp = tid >> 3, g = tid & 7;
            int r = rp * 2, c = g * 8;
            float o0[8] = {0,0,0,0,0,0,0,0}, o1[8] = {0,0,0,0,0,0,0,0};
            float wp[5];
            #pragma unroll
            for (int i = 0; i < 6; i++) {
                float t[12];
                #pragma unroll
                for (int k = 0; k < 3; k++) {
                    uint2 u = *(const uint2*)&sGh[(r + i) * GP + c + k * 4];
                    float2 f0 = __half22float2(*(const __half2*)&u.x);
                    float2 f1 = __half22float2(*(const __half2*)&u.y);
                    t[k*4 + 0] = f0.x; t[k*4 + 1] = f0.y;
                    t[k*4 + 2] = f1.x; t[k*4 + 3] = f1.y;
                }
                if (i > 0) {
                    #pragma unroll
                    for (int j = 0; j < 8; j++)
                        o1[j] += wp[0]*t[j] + wp[1]*t[j+1] + wp[2]*t[j+2]
                               + wp[3]*t[j+3] + wp[4]*t[j+4];
                }
                if (i < 5) {
                    float wc[5];
                    #pragma unroll
                    for (int v = 0; v < 5; v++) wc[v] = wbuf[45 + i * 5 + v];
                    #pragma unroll
                    for (int j = 0; j < 8; j++)
                        o0[j] += wc[0]*t[j] + wc[1]*t[j+1] + wc[2]*t[j+2]
                               + wc[3]*t[j+3] + wc[4]*t[j+4];
                    #pragma unroll
                    for (int v = 0; v < 5; v++) wp[v] = wc[v];
                }
            }
            float* ob = out + (size_t)b * HW + (size_t)(y0 + r) * IMG_W + x0 + c;
            *(float4*)ob               = make_float4(o0[0], o0[1], o0[2], o0[3]);
            *(float4*)(ob + 4)         = make_float4(o0[4], o0[5], o0[6], o0[7]);
            *(float4*)(ob + IMG_W)     = make_float4(o1[0], o1[1], o1[2], o1[3]);
            *(float4*)(ob + IMG_W + 4) = make_float4(o1[4], o1[5], o1[6], o1[7]);
        }
    } else {
        // ================= border path: staged stages 3, 4 (fp32) =============
        float* const sG = buf1;
        float* const sT = buf2;

        if (tid < 17 * 9) {
            float w[9];
            #pragma unroll
            for (int i = 0; i < 9; i++) w[i] = wbuf[27 + i];
            int rp = tid / 9, g = tid - rp * 9;
            int r = rp * 2, c = g * 8;
            float v0[8] = {0,0,0,0,0,0,0,0}, v1[8] = {0,0,0,0,0,0,0,0};
            #pragma unroll
            for (int i = 0; i < 4; i++) {
                float t[12];
                *(float4*)&t[0] = *(const float4*)&sG[(r + i) * GP + c];
                *(float4*)&t[4] = *(const float4*)&sG[(r + i) * GP + c + 4];
                *(float4*)&t[8] = *(const float4*)&sG[(r + i) * GP + c + 8];
                if (i < 3) {
                    #pragma unroll
                    for (int j = 0; j < 8; j++)
                        v0[j] += w[i*3]*t[j] + w[i*3+1]*t[j+1] + w[i*3+2]*t[j+2];
                }
                if (i > 0) {
                    #pragma unroll
                    for (int j = 0; j < 8; j++)
                        v1[j] += w[(i-1)*3]*t[j] + w[(i-1)*3+1]*t[j+1] + w[(i-1)*3+2]*t[j+2];
                }
            }
            int py = y0 + r - 1, px = x0 + c - 1;
            bool iny0 = (unsigned)py       < (unsigned)IMG_H;
            bool iny1 = (unsigned)(py + 1) < (unsigned)IMG_H;
            #pragma unroll
            for (int j = 0; j < 8; j++) {
                bool inx = (unsigned)(px + j) < (unsigned)IMG_W;
                v0[j] = (iny0 && inx) ? v0[j] : 0.f;
                v1[j] = (iny1 && inx) ? v1[j] : 0.f;
            }
            *(float4*)&sT[r * TP + c]           = make_float4(v0[0], v0[1], v0[2], v0[3]);
            *(float4*)&sT[r * TP + c + 4]       = make_float4(v0[4], v0[5], v0[6], v0[7]);
            *(float4*)&sT[(r + 1) * TP + c]     = make_float4(v1[0], v1[1], v1[2], v1[3]);
            *(float4*)&sT[(r + 1) * TP + c + 4] = make_float4(v1[4], v1[5], v1[6], v1[7]);
        }
        __syncthreads();

        if (tid < 16 * 8) {
            float w[9];
            #pragma unroll
            for (int i = 0; i < 9; i++) w[i] = wbuf[36 + i];
            int rp = tid >> 3, g = tid & 7;
            int r = rp * 2, c = g * 8;
            float v0[8] = {0,0,0,0,0,0,0,0}, v1[8] = {0,0,0,0,0,0,0,0};
            #pragma unroll
            for (int i = 0; i < 4; i++) {
                float t[12];
                *(float4*)&t[0] = *(const float4*)&sT[(r + i) * TP + c];
                *(float4*)&t[4] = *(const float4*)&sT[(r + i) * TP + c + 4];
                *(float4*)&t[8] = *(const float4*)&sT[(r + i) * TP + c + 8];
                if (i < 3) {
                    #pragma unroll
                    for (int j = 0; j < 8; j++)
                        v0[j] += w[i*3]*t[j] + w[i*3+1]*t[j+1] + w[i*3+2]*t[j+2];
                }
                if (i > 0) {
                    #pragma unroll
                    for (int j = 0; j < 8; j++)
                        v1[j] += w[(i-1)*3]*t[j] + w[(i-1)*3+1]*t[j+1] + w[(i-1)*3+2]*t[j+2];
                }
            }
            float* ob = out + (size_t)b * HW + (size_t)(y0 + r) * IMG_W + x0 + c;
            *(float4*)ob                 = make_float4(v0[0], v0[1], v0[2], v0[3]);
            *(float4*)(ob + 4)           = make_float4(v0[4], v0[5], v0[6], v0[7]);
            *(float4*)(ob + IMG_W)       = make_float4(v1[0], v1[1], v1[2], v1[3]);
            *(float4*)(ob + IMG_W + 4)   = make_float4(v1[4], v1[5], v1[6], v1[7]);
        }
    }
}

extern "C" void kernel_launch(void* const* d_in, const int* in_sizes, int n_in,
                              void* d_out, int out_size) {
    const float* img = (const float*)d_in[0];
    const float* gw  = (const float*)d_in[1];
    const float* sxw = (const float*)d_in[2];
    const float* syw = (const float*)d_in[3];
    const float* dw  = (const float*)d_in[4];
    const float* nw  = (const float*)d_in[5];
    float* out = (float*)d_out;

    int C = in_sizes[1] / 9;
    if (C < 1) C = 1;
    int B = in_sizes[0] / (C * HW);
    if (B < 1) B = 1;

    dim3 grid(IMG_W / TW, IMG_H / TH, B);
    canny_fused<<<grid, NT>>>(img, gw, sxw, syw, dw, nw, out, C, 1.0f / (float)C);
}